// round 3
// baseline (speedup 1.0000x reference)
#include <cuda_runtime.h>
#include <cuda_bf16.h>
#include <stdint.h>

// out[m] = x[m]·W + b + 0.5*||x[m]V||^2 - 0.5*(sum_i x[m,i])^2 * ||V.sum(0)||^2
// x: (16384,4096) f32, W: (1,4096) f32, b: (1,) f32, V: (4096,128) f32, out f32.

#define MROWS 16384
#define KDIM  4096
#define NDIM  128
#define KC    64                  // K per staged B chunk
#define NCH   (KDIM / KC)         // 64 chunks
#define NSTEP (KDIM / 16)         // 256 k16 steps
#define BROW  144                 // padded smem row stride (bytes) for V^T chunk
#define BBUF  (128 * BROW)        // 18432 bytes per buffer

__device__ __nv_bfloat16 g_Vt[(size_t)NDIM * KDIM];  // V^T bf16 [n][k]
__device__ float g_spart[64 * NDIM];                 // partial column sums of V
__device__ float g_s2;                               // ||V.sum(0)||^2

// ---------------- helpers ----------------

static __device__ __forceinline__ uint32_t smem_u32(const void* p) {
    uint32_t r;
    asm("{ .reg .u64 t; cvta.to.shared.u64 t, %1; cvt.u32.u64 %0, t; }"
        : "=r"(r) : "l"(p));
    return r;
}

static __device__ __forceinline__ uint32_t pack2(float lo, float hi) {
    __nv_bfloat162 h = __float22bfloat162_rn(make_float2(lo, hi));
    return *reinterpret_cast<uint32_t*>(&h);
}

#define MMA_OP(d, a0, a1, a2, a3, b0, b1)                                  \
    asm volatile(                                                          \
        "mma.sync.aligned.m16n8k16.row.col.f32.bf16.bf16.f32 "             \
        "{%0,%1,%2,%3}, {%4,%5,%6,%7}, {%8,%9}, {%0,%1,%2,%3};"            \
        : "+f"((d)[0]), "+f"((d)[1]), "+f"((d)[2]), "+f"((d)[3])           \
        : "r"(a0), "r"(a1), "r"(a2), "r"(a3), "r"(b0), "r"(b1))

#define LDSM_X4(r0, r1, r2, r3, addr)                                      \
    asm volatile("ldmatrix.sync.aligned.m8n8.x4.shared.b16 "               \
                 "{%0,%1,%2,%3}, [%4];"                                    \
                 : "=r"(r0), "=r"(r1), "=r"(r2), "=r"(r3) : "r"(addr))

// ---------------- prep kernels ----------------

// 64 blocks x 64 K-rows of V: coalesced read, smem transpose,
// write V^T bf16 + fp32 partial column sums.
__global__ void prep_kernel(const float* __restrict__ V) {
    __shared__ __align__(16) __nv_bfloat16 sm[128 * 66];
    __shared__ float ps[256];
    const int t = threadIdx.x;
    const int b = blockIdx.x;
    const int k0 = b * 64;
    const int n = t & 127;
    const int half = t >> 7;

    float partial = 0.f;
#pragma unroll
    for (int i = 0; i < 32; i++) {
        int kk = 2 * i + half;
        float v = V[(size_t)(k0 + kk) * NDIM + n];
        partial += v;
        sm[n * 66 + kk] = __float2bfloat16(v);
    }
    ps[t] = partial;
    __syncthreads();
    if (t < 128) g_spart[b * 128 + t] = ps[t] + ps[t + 128];

    const int r = t >> 1, part = t & 1;
    const uint32_t* src = (const uint32_t*)((const char*)sm + r * 132 + part * 64);
    uint32_t v0[16];
#pragma unroll
    for (int i = 0; i < 16; i++) v0[i] = src[i];
    uint4* dst = (uint4*)(g_Vt + (size_t)r * KDIM + k0 + part * 32);
#pragma unroll
    for (int i = 0; i < 4; i++)
        dst[i] = make_uint4(v0[4*i], v0[4*i+1], v0[4*i+2], v0[4*i+3]);
}

__global__ void s2_kernel() {
    __shared__ float sh[128];
    int t = threadIdx.x;
    float s = 0.f;
    for (int b2 = 0; b2 < 64; b2++) s += g_spart[b2 * 128 + t];
    sh[t] = s * s;
    __syncthreads();
    for (int o = 64; o > 0; o >>= 1) {
        if (t < o) sh[t] += sh[t + o];
        __syncthreads();
    }
    if (t == 0) g_s2 = sh[0];
}

// ---------------- main kernel ----------------
// 512 threads = 16 warps = 4 m-strips (32 rows) x 4 n-quads (32 cols).
// A (x, fp32) loaded straight from gmem into mma fragments (reg prefetch d=2),
// with fp32 xsum / x·W folded in. B (V^T bf16) staged in smem, double-buffered
// per K=64 chunk, fragments via ldmatrix.x4 on 144B-padded rows.

__global__ void __launch_bounds__(512, 1) fm_main(
    const float* __restrict__ x, const float* __restrict__ W,
    const float* __restrict__ bias, float* __restrict__ out)
{
    __shared__ __align__(16) unsigned char bsm[2 * BBUF];   // 36864 B
    __shared__ float red[128][4];
    __shared__ float sxs[128], sws[128];

    const int t = threadIdx.x;
    const int wid = t >> 5, lane = t & 31;
    const int mstrip = wid & 3;     // spreads m-strips across SMSPs
    const int nquad  = wid >> 2;
    const int lq = lane >> 2, lr = lane & 3;
    const int mbase = blockIdx.x * 128;

    // ---- A pointers: xr[mt*2+rh] -> row (mstrip*32 + mt*16 + rh*8 + lq), col 2*lr
    const float* xr[4];
    {
        const float* xb = x + (size_t)(mbase + mstrip * 32 + lq) * KDIM + 2 * lr;
        xr[0] = xb;
        xr[1] = xb + (size_t)8 * KDIM;
        xr[2] = xb + (size_t)16 * KDIM;
        xr[3] = xb + (size_t)24 * KDIM;
    }
    const float* pW = W + 2 * lr;

    // ---- B ldmatrix lane addressing (x4: lanes 0-7 m0, 8-15 m1, 16-23 m2, 24-31 m3)
    // m0=(nt0,k0..7), m1=(nt0,k8..15), m2=(nt1,k0..7), m3=(nt1,k8..15)
    const uint32_t bsm0 = smem_u32(bsm);
    const int g2 = lane >> 3;
    const int ntsel = g2 >> 1, khalf = g2 & 1;
    const uint32_t lds0 = bsm0 + (uint32_t)(nquad * 32 + ntsel * 8 + (lane & 7)) * BROW
                        + khalf * 16;

    // ---- B staging assignment: thread -> (row sn, 32B part sp)
    const int sn = t >> 2, sp = t & 3;
    const unsigned char* vsrc = (const unsigned char*)g_Vt + (size_t)sn * (KDIM * 2) + sp * 32;
    unsigned char* bdst = bsm + sn * BROW + sp * 32;

    float acc[2][4][4];
#pragma unroll
    for (int i = 0; i < 2; i++)
#pragma unroll
        for (int j = 0; j < 4; j++)
#pragma unroll
            for (int k = 0; k < 4; k++) acc[i][j][k] = 0.f;

    float sx[4] = {0.f, 0.f, 0.f, 0.f};
    float sw[4] = {0.f, 0.f, 0.f, 0.f};

    // ab[buf][mt*4 + rh*2 + half] (half: 0=k0..7, 1=k8..15)
    float2 ab[2][8];

#define LOADA(b, s) do {                                                    \
        const int _ko = (s) * 16;                                           \
        ab[b][0] = *(const float2*)(xr[0] + _ko);                           \
        ab[b][1] = *(const float2*)(xr[0] + _ko + 8);                       \
        ab[b][2] = *(const float2*)(xr[1] + _ko);                           \
        ab[b][3] = *(const float2*)(xr[1] + _ko + 8);                       \
        ab[b][4] = *(const float2*)(xr[2] + _ko);                           \
        ab[b][5] = *(const float2*)(xr[2] + _ko + 8);                       \
        ab[b][6] = *(const float2*)(xr[3] + _ko);                           \
        ab[b][7] = *(const float2*)(xr[3] + _ko + 8);                       \
    } while (0)

    // prefetch A steps 0,1 ; stage B chunk 0
    LOADA(0, 0);
    LOADA(1, 1);
    {
        uint4 a0 = *(const uint4*)(vsrc);
        uint4 a1 = *(const uint4*)(vsrc + 16);
        ((uint4*)bdst)[0] = a0;
        ((uint4*)(bdst + 16))[0] = a1;
    }
    __syncthreads();

#pragma unroll 1
    for (int c = 0; c < NCH; c++) {
        // issue stage loads for chunk c+1 early (L2-resident V^T)
        uint4 sv0, sv1;
        const bool more = (c + 1 < NCH);
        if (more) {
            const unsigned char* s2p = vsrc + (size_t)(c + 1) * 128;
            sv0 = *(const uint4*)(s2p);
            sv1 = *(const uint4*)(s2p + 16);
        }
        const uint32_t bufoff = (uint32_t)(c & 1) * BBUF;

#pragma unroll
        for (int ks = 0; ks < 4; ks++) {
            const int s = c * 4 + ks;
            const int bi = ks & 1;

            // ---- A fragments (bf16x2) from prefetched fp32
            uint32_t afr[2][4];
#pragma unroll
            for (int mt = 0; mt < 2; mt++) {
                const float2 lo0 = ab[bi][mt * 4 + 0];  // row lo, k0..7
                const float2 hi0 = ab[bi][mt * 4 + 1];  // row lo, k8..15
                const float2 lo1 = ab[bi][mt * 4 + 2];  // row hi, k0..7
                const float2 hi1 = ab[bi][mt * 4 + 3];  // row hi, k8..15
                afr[mt][0] = pack2(lo0.x, lo0.y);
                afr[mt][1] = pack2(lo1.x, lo1.y);
                afr[mt][2] = pack2(hi0.x, hi0.y);
                afr[mt][3] = pack2(hi1.x, hi1.y);
            }

            // ---- fp32 side sums (only nquad 0 to avoid duplication)
            if (nquad == 0) {
                const float2 wlo = *(const float2*)(pW + s * 16);
                const float2 whi = *(const float2*)(pW + s * 16 + 8);
#pragma unroll
                for (int mt = 0; mt < 2; mt++) {
                    const float2 lo0 = ab[bi][mt * 4 + 0];
                    const float2 hi0 = ab[bi][mt * 4 + 1];
                    const float2 lo1 = ab[bi][mt * 4 + 2];
                    const float2 hi1 = ab[bi][mt * 4 + 3];
                    sx[mt * 2 + 0] += (lo0.x + lo0.y) + (hi0.x + hi0.y);
                    sx[mt * 2 + 1] += (lo1.x + lo1.y) + (hi1.x + hi1.y);
                    sw[mt * 2 + 0] += lo0.x * wlo.x + lo0.y * wlo.y
                                    + hi0.x * whi.x + hi0.y * whi.y;
                    sw[mt * 2 + 1] += lo1.x * wlo.x + lo1.y * wlo.y
                                    + hi1.x * whi.x + hi1.y * whi.y;
                }
            }

            // ---- prefetch A for step s+2 (reuses just-consumed buffer)
            if (c < NCH - 1 || ks < 2) LOADA(bi, s + 2);

            // ---- B fragments via ldmatrix
            uint32_t bf[4][2];
            {
                const uint32_t a0 = lds0 + bufoff + ks * 32;
                LDSM_X4(bf[0][0], bf[0][1], bf[1][0], bf[1][1], a0);
                LDSM_X4(bf[2][0], bf[2][1], bf[3][0], bf[3][1], a0 + 16 * BROW);
            }

            // ---- 8 HMMA
#pragma unroll
            for (int mt = 0; mt < 2; mt++)
#pragma unroll
                for (int nt = 0; nt < 4; nt++)
                    MMA_OP(acc[mt][nt], afr[mt][0], afr[mt][1], afr[mt][2], afr[mt][3],
                           bf[nt][0], bf[nt][1]);
        }

        if (more) {
            unsigned char* d = bdst + (((c + 1) & 1) ? BBUF : 0);
            ((uint4*)d)[0] = sv0;
            ((uint4*)(d + 16))[0] = sv1;
        }
        __syncthreads();
    }

    // ---------------- epilogue ----------------
    // term1 partials: rows (mstrip*32 + mt*16 + {lq, lq+8}), reduce over lane cols
#pragma unroll
    for (int mt = 0; mt < 2; mt++) {
        float p0 = 0.f, p1 = 0.f;
#pragma unroll
        for (int nt = 0; nt < 4; nt++) {
            p0 += acc[mt][nt][0] * acc[mt][nt][0] + acc[mt][nt][1] * acc[mt][nt][1];
            p1 += acc[mt][nt][2] * acc[mt][nt][2] + acc[mt][nt][3] * acc[mt][nt][3];
        }
        p0 += __shfl_xor_sync(0xffffffffu, p0, 1);
        p0 += __shfl_xor_sync(0xffffffffu, p0, 2);
        p1 += __shfl_xor_sync(0xffffffffu, p1, 1);
        p1 += __shfl_xor_sync(0xffffffffu, p1, 2);
        if (lr == 0) {
            red[mstrip * 32 + mt * 16 + lq][nquad]     = p0;
            red[mstrip * 32 + mt * 16 + 8 + lq][nquad] = p1;
        }
    }

    if (nquad == 0) {
#pragma unroll
        for (int i = 0; i < 4; i++) {
            sx[i] += __shfl_xor_sync(0xffffffffu, sx[i], 1);
            sx[i] += __shfl_xor_sync(0xffffffffu, sx[i], 2);
            sw[i] += __shfl_xor_sync(0xffffffffu, sw[i], 1);
            sw[i] += __shfl_xor_sync(0xffffffffu, sw[i], 2);
        }
        if (lr == 0) {
#pragma unroll
            for (int i = 0; i < 4; i++) {
                const int row = mstrip * 32 + (i >> 1) * 16 + (i & 1) * 8 + lq;
                sxs[row] = sx[i];
                sws[row] = sw[i];
            }
        }
    }
    __syncthreads();

    if (t < 128) {
        const float t1 = red[t][0] + red[t][1] + red[t][2] + red[t][3];
        const float s_ = sxs[t];
        out[mbase + t] = sws[t] + bias[0] + 0.5f * t1 - 0.5f * s_ * s_ * g_s2;
    }
}

// ---------------- launch ----------------

extern "C" void kernel_launch(void* const* d_in, const int* in_sizes, int n_in,
                              void* d_out, int out_size) {
    (void)in_sizes; (void)n_in; (void)out_size;
    const float* x = (const float*)d_in[0];
    const float* W = (const float*)d_in[1];
    const float* b = (const float*)d_in[2];
    const float* V = (const float*)d_in[3];
    float* out = (float*)d_out;

    prep_kernel<<<64, 256>>>(V);
    s2_kernel<<<1, 128>>>();
    fm_main<<<MROWS / 128, 512>>>(x, W, b, out);
}

// round 4
// speedup vs baseline: 2.4651x; 2.4651x over previous
#include <cuda_runtime.h>
#include <cuda_bf16.h>
#include <stdint.h>

// out[m] = x[m]·W + b + 0.5*||x[m]V||^2 - 0.5*(sum_i x[m,i])^2 * ||V.sum(0)||^2
// x: (16384,4096) f32, W: (1,4096) f32, b: (1,) f32, V: (4096,128) f32, out f32.

#define MROWS 16384
#define KDIM  4096
#define NDIM  128
#define KC    64                   // K per chunk
#define NCH   (KDIM / KC)          // 64
#define AROW  144                  // padded smem row stride (bytes), 128B data + 16B pad
#define ABUF  (128 * AROW)         // 18432 B per buffer (A and B identical shape)

// dynamic smem: A[2] | B[2] | red[128][2] | sxs[128] | sws[128]
#define OF_B   (2 * ABUF)
#define OF_RED (4 * ABUF)
#define OF_SXS (OF_RED + 1024)
#define OF_SWS (OF_SXS + 512)
#define SMEM_TOTAL (OF_SWS + 512)  // 75776 B

__device__ __nv_bfloat16 g_Vt[(size_t)NCH * NDIM * KC];  // chunk-major: [c][n][kk]
__device__ float g_spart[64 * NDIM];
__device__ float g_s2;

// ---------------- helpers ----------------

static __device__ __forceinline__ uint32_t smem_u32(const void* p) {
    uint32_t r;
    asm("{ .reg .u64 t; cvta.to.shared.u64 t, %1; cvt.u32.u64 %0, t; }"
        : "=r"(r) : "l"(p));
    return r;
}

static __device__ __forceinline__ uint32_t pack2(float lo, float hi) {
    __nv_bfloat162 h = __float22bfloat162_rn(make_float2(lo, hi));
    return *reinterpret_cast<uint32_t*>(&h);
}

#define MMA_OP(d, a0, a1, a2, a3, b0, b1)                                  \
    asm volatile(                                                          \
        "mma.sync.aligned.m16n8k16.row.col.f32.bf16.bf16.f32 "             \
        "{%0,%1,%2,%3}, {%4,%5,%6,%7}, {%8,%9}, {%0,%1,%2,%3};"            \
        : "+f"((d)[0]), "+f"((d)[1]), "+f"((d)[2]), "+f"((d)[3])           \
        : "r"(a0), "r"(a1), "r"(a2), "r"(a3), "r"(b0), "r"(b1))

#define LDSM_X4(r0, r1, r2, r3, addr)                                      \
    asm volatile("ldmatrix.sync.aligned.m8n8.x4.shared.b16 "               \
                 "{%0,%1,%2,%3}, [%4];"                                    \
                 : "=r"(r0), "=r"(r1), "=r"(r2), "=r"(r3) : "r"(addr))

// ---------------- prep kernels ----------------

// 64 blocks, block b handles K-rows [64b, 64b+64) == chunk b.
// Coalesced read of V, smem transpose, write chunk-major bf16 V^T + partial sums.
__global__ void prep_kernel(const float* __restrict__ V) {
    __shared__ __align__(16) __nv_bfloat16 sm[128 * 66];
    __shared__ float ps[256];
    const int t = threadIdx.x;
    const int b = blockIdx.x;
    const int k0 = b * 64;
    const int n = t & 127;
    const int half = t >> 7;

    float partial = 0.f;
#pragma unroll
    for (int i = 0; i < 32; i++) {
        int kk = 2 * i + half;
        float v = V[(size_t)(k0 + kk) * NDIM + n];
        partial += v;
        sm[n * 66 + kk] = __float2bfloat16(v);
    }
    ps[t] = partial;
    __syncthreads();
    if (t < 128) g_spart[b * 128 + t] = ps[t] + ps[t + 128];

    // dst: chunk-major block b, row n (128B), fully coalesced STG
    const int r = t >> 1, part = t & 1;
    const uint32_t* src = (const uint32_t*)((const char*)sm + r * 132 + part * 64);
    uint32_t v0[16];
#pragma unroll
    for (int i = 0; i < 16; i++) v0[i] = src[i];
    uint4* dst = (uint4*)((char*)g_Vt + (size_t)b * 16384 + (size_t)r * 128 + part * 64);
#pragma unroll
    for (int i = 0; i < 4; i++)
        dst[i] = make_uint4(v0[4*i], v0[4*i+1], v0[4*i+2], v0[4*i+3]);
}

__global__ void s2_kernel() {
    __shared__ float sh[128];
    int t = threadIdx.x;
    float s = 0.f;
    for (int b2 = 0; b2 < 64; b2++) s += g_spart[b2 * 128 + t];
    sh[t] = s * s;
    __syncthreads();
    for (int o = 64; o > 0; o >>= 1) {
        if (t < o) sh[t] += sh[t + o];
        __syncthreads();
    }
    if (t == 0) g_s2 = sh[0];
}

// ---------------- main kernel ----------------
// 256 thr = 8 warps = 4 m-strips (m32) x 2 n-halves (n64). CTA tile 128x128.
// All gmem access coalesced; fragments via ldmatrix from 144B-padded smem.

__global__ void __launch_bounds__(256, 1) fm_main(
    const float* __restrict__ x, const float* __restrict__ W,
    const float* __restrict__ bias, float* __restrict__ out)
{
    extern __shared__ __align__(16) char smem[];
    float (*red)[2] = (float(*)[2])(smem + OF_RED);
    float* sxs = (float*)(smem + OF_SXS);
    float* sws = (float*)(smem + OF_SWS);

    const int t = threadIdx.x;
    const int wid = t >> 5, lane = t & 31;
    const int mstrip = wid & 3;
    const int nhalf  = wid >> 2;
    const int mbase = blockIdx.x * 128;

    const uint32_t sAu = smem_u32(smem);
    const uint32_t sBu = sAu + OF_B;

    // ---- gmem pointers (coalesced: idx16 = i*256 + t over the chunk tile)
    // A: row = i*16 + (t>>4), col16-within-chunk = t&15
    const char* xb = (const char*)x + ((size_t)(mbase + (t >> 4)) << 14) + (t & 15) * 16;
    // B: chunk-major g_Vt, thread reads 16B at j*4096 + t*16
    const char* vb = (const char*)g_Vt + (size_t)t * 16;
    const float4* wp = (const float4*)W + (t & 15);

    // ---- STS addresses (bank-conflict free, checked mod-8/16)
    const uint32_t asts = sAu + (t >> 4) * AROW + (t & 15) * 8;   // 8B per i-slot
    const uint32_t bsts = sBu + (t >> 3) * AROW + (t & 7) * 16;   // 16B per j-slot

    // ---- ldmatrix addresses
    // A m16k16: lanes0-7 m0(rows0-7,k0), 8-15 m1(rows8-15,k0), 16-23 m2(k8), 24-31 m3
    const uint32_t alds = sAu + (uint32_t)(mstrip * 32 + (lane & 15)) * AROW
                        + (lane >> 4) * 16;
    // B pair of n8-tiles: lanes0-7 nt0 k0, 8-15 nt0 k8, 16-23 nt1 k0, 24-31 nt1 k8
    const uint32_t blds = sBu + (uint32_t)(nhalf * 64 + (lane >> 4) * 8 + (lane & 7)) * AROW
                        + ((lane >> 3) & 1) * 16;

    float acc[2][8][4];
#pragma unroll
    for (int i = 0; i < 2; i++)
#pragma unroll
        for (int j = 0; j < 8; j++)
#pragma unroll
            for (int k = 0; k < 4; k++) acc[i][j][k] = 0.f;

    float sx[8], sw[8];
#pragma unroll
    for (int i = 0; i < 8; i++) { sx[i] = 0.f; sw[i] = 0.f; }

    float4 areg[8];
    uint4  breg[4];

#define LOADA(c) do {                                                       \
        _Pragma("unroll")                                                   \
        for (int i = 0; i < 8; i++)                                         \
            areg[i] = *(const float4*)(xb + (size_t)i * 262144 + (c) * 256);\
    } while (0)

#define LOADB(c) do {                                                       \
        _Pragma("unroll")                                                   \
        for (int j = 0; j < 4; j++)                                         \
            breg[j] = *(const uint4*)(vb + (size_t)(c) * 16384 + j * 4096); \
    } while (0)

    // sums use fp32 values of chunk c; stores convert to bf16 into buffer `buf`
#define SUMS_STS(c, buf) do {                                               \
        const float4 w4 = wp[(c) * 16];                                     \
        const uint32_t ao_ = (uint32_t)(buf) * ABUF;                        \
        _Pragma("unroll")                                                   \
        for (int i = 0; i < 8; i++) {                                       \
            const float4 q = areg[i];                                       \
            sx[i] += (q.x + q.y) + (q.z + q.w);                             \
            sw[i] += q.x * w4.x + q.y * w4.y + q.z * w4.z + q.w * w4.w;     \
            const uint32_t p0 = pack2(q.x, q.y), p1 = pack2(q.z, q.w);      \
            asm volatile("st.shared.v2.b32 [%0], {%1,%2};"                  \
                         :: "r"(asts + ao_ + i * 2304), "r"(p0), "r"(p1));  \
        }                                                                   \
        _Pragma("unroll")                                                   \
        for (int j = 0; j < 4; j++)                                         \
            asm volatile("st.shared.v4.b32 [%0], {%1,%2,%3,%4};"            \
                         :: "r"(bsts + ao_ + j * 4608), "r"(breg[j].x),     \
                            "r"(breg[j].y), "r"(breg[j].z), "r"(breg[j].w));\
    } while (0)

    // prologue: chunk 0
    LOADA(0); LOADB(0);
    SUMS_STS(0, 0);
    __syncthreads();

#pragma unroll 1
    for (int c = 0; c < NCH; c++) {
        const bool more = (c + 1 < NCH);
        if (more) { LOADA(c + 1); LOADB(c + 1); }

        const uint32_t ao = (uint32_t)(c & 1) * ABUF;
#pragma unroll
        for (int ks = 0; ks < 4; ks++) {
            uint32_t afr[2][4];
            LDSM_X4(afr[0][0], afr[0][1], afr[0][2], afr[0][3],
                    alds + ao + ks * 32);
            LDSM_X4(afr[1][0], afr[1][1], afr[1][2], afr[1][3],
                    alds + ao + ks * 32 + 16 * AROW);
            uint32_t bfr[8][2];
#pragma unroll
            for (int p = 0; p < 4; p++)
                LDSM_X4(bfr[2*p][0], bfr[2*p][1], bfr[2*p+1][0], bfr[2*p+1][1],
                        blds + ao + ks * 32 + p * 16 * AROW);
#pragma unroll
            for (int mt = 0; mt < 2; mt++)
#pragma unroll
                for (int nt = 0; nt < 8; nt++)
                    MMA_OP(acc[mt][nt], afr[mt][0], afr[mt][1], afr[mt][2],
                           afr[mt][3], bfr[nt][0], bfr[nt][1]);
        }

        if (more) SUMS_STS(c + 1, (c + 1) & 1);
        __syncthreads();
    }

    // ---------------- epilogue ----------------
    // term1: per warp, rows mstrip*32 + mt*16 + {lane>>2, (lane>>2)+8}
#pragma unroll
    for (int mt = 0; mt < 2; mt++) {
        float p0 = 0.f, p1 = 0.f;
#pragma unroll
        for (int nt = 0; nt < 8; nt++) {
            p0 += acc[mt][nt][0] * acc[mt][nt][0] + acc[mt][nt][1] * acc[mt][nt][1];
            p1 += acc[mt][nt][2] * acc[mt][nt][2] + acc[mt][nt][3] * acc[mt][nt][3];
        }
        p0 += __shfl_xor_sync(0xffffffffu, p0, 1);
        p0 += __shfl_xor_sync(0xffffffffu, p0, 2);
        p1 += __shfl_xor_sync(0xffffffffu, p1, 1);
        p1 += __shfl_xor_sync(0xffffffffu, p1, 2);
        if ((lane & 3) == 0) {
            red[mstrip * 32 + mt * 16 + (lane >> 2)][nhalf]     = p0;
            red[mstrip * 32 + mt * 16 + 8 + (lane >> 2)][nhalf] = p1;
        }
    }

    // side sums: reduce over the 16 threads sharing (t>>4)
#pragma unroll
    for (int i = 0; i < 8; i++) {
#pragma unroll
        for (int o = 8; o > 0; o >>= 1) {
            sx[i] += __shfl_xor_sync(0xffffffffu, sx[i], o);
            sw[i] += __shfl_xor_sync(0xffffffffu, sw[i], o);
        }
    }
    if ((t & 15) == 0) {
        const int h = t >> 4;
#pragma unroll
        for (int i = 0; i < 8; i++) {
            sxs[i * 16 + h] = sx[i];
            sws[i * 16 + h] = sw[i];
        }
    }
    __syncthreads();

    if (t < 128) {
        const float t1 = red[t][0] + red[t][1];
        const float s_ = sxs[t];
        out[mbase + t] = sws[t] + bias[0] + 0.5f * t1 - 0.5f * s_ * s_ * g_s2;
    }
}

// ---------------- launch ----------------

extern "C" void kernel_launch(void* const* d_in, const int* in_sizes, int n_in,
                              void* d_out, int out_size) {
    (void)in_sizes; (void)n_in; (void)out_size;
    const float* x = (const float*)d_in[0];
    const float* W = (const float*)d_in[1];
    const float* b = (const float*)d_in[2];
    const float* V = (const float*)d_in[3];
    float* out = (float*)d_out;

    cudaFuncSetAttribute(fm_main, cudaFuncAttributeMaxDynamicSharedMemorySize, SMEM_TOTAL);

    prep_kernel<<<64, 256>>>(V);
    s2_kernel<<<1, 128>>>();
    fm_main<<<MROWS / 128, 256, SMEM_TOTAL>>>(x, W, b, out);
}